// round 3
// baseline (speedup 1.0000x reference)
#include <cuda_runtime.h>

// PGCNCritic fused kernel, fp32 SIMT baseline.
// One CTA per batch element (grid = 16384, 256 threads).
//
// Phases (per CTA):
//  1. Stage obs + embedding weights to SMEM; build adjacency bitmasks + d^-1/2 via ballot.
//  2. Embedding -> x (64 nodes x 64 hidden) in SMEM.
//  3. 3x GCN layer: scale rows by dinv, sparse-aggregate via bitmask (warp-uniform),
//     scale by dinv_i, then 64x64x64 register-tiled matmul with W in SMEM, ReLU.
//  4. Head: mean over device nodes; u[128] = bf1 + Wf1_mean^T mean + Wf1_srv^T h63
//     (constant over nodes -> 3x FLOP reduction); z_i = Wf1_dev^T h_i + u;
//     out_i = relu(z_i) . Wf2 + bf2, reduced via shfl.

#define FULLMASK 0xffffffffu

__global__ __launch_bounds__(256, 4)
void pgcn_kernel(
    const float* __restrict__ dev_obs,   // (B,63,14)
    const float* __restrict__ srv_obs,   // (B,3)
    const float* __restrict__ adj,       // (B,64,64)
    const float* __restrict__ W_dev,     // (14,64)
    const float* __restrict__ b_dev,     // (64)
    const float* __restrict__ W_srv,     // (3,64)
    const float* __restrict__ b_srv,     // (64)
    const float* __restrict__ W1, const float* __restrict__ b1,
    const float* __restrict__ W2, const float* __restrict__ b2,
    const float* __restrict__ W3, const float* __restrict__ b3,
    const float* __restrict__ Wf1,       // (192,128)
    const float* __restrict__ bf1,       // (128)
    const float* __restrict__ Wf2,       // (128)
    const float* __restrict__ bf2,       // (1)
    float* __restrict__ out)             // (B,63)
{
    __shared__ __align__(16) float s_a[4096];      // node features (64x64)
    __shared__ __align__(16) float s_pool[8192];   // layers: [t(4096) | W(4096)]; head: Wf1_dev(64x128)
    __shared__ float s_obs[896];                   // 882 device obs + 3 server obs
    __shared__ unsigned s_mlo[64], s_mhi[64];      // adjacency row bitmasks
    __shared__ float s_dinv[64];
    __shared__ float s_mean[64];
    __shared__ float s_u[128];
    __shared__ float s_wf2[128];

    const int b    = blockIdx.x;
    const int tid  = threadIdx.x;
    const int lane = tid & 31;
    const int warp = tid >> 5;

    // ---------------- Phase 1: stage inputs, build adjacency masks ----------------
    for (int i = tid; i < 882; i += 256) s_obs[i] = dev_obs[b * 882 + i];
    if (tid < 3) s_obs[882 + tid] = srv_obs[b * 3 + tid];
    // embedding weights into s_pool: W_dev (896 floats) then W_srv (192 floats)
    for (int i = tid; i < 896; i += 256) s_pool[i] = W_dev[i];
    if (tid < 192) s_pool[896 + tid] = W_srv[tid];

    // adjacency: each warp does 8 rows; values are exactly 0.0 or 1.0
    {
        const float* arow = adj + (size_t)b * 4096;
        for (int r = warp; r < 64; r += 8) {
            float v0 = arow[r * 64 + lane];
            float v1 = arow[r * 64 + 32 + lane];
            unsigned m0 = __ballot_sync(FULLMASK, v0 != 0.0f);
            unsigned m1 = __ballot_sync(FULLMASK, v1 != 0.0f);
            if (lane == 0) {
                s_mlo[r] = m0;
                s_mhi[r] = m1;
                float deg = (float)(__popc(m0) + __popc(m1));
                s_dinv[r] = rsqrtf(fmaxf(deg, 1.0f));
            }
        }
    }
    __syncthreads();

    // ---------------- Phase 2: embedding -> s_a ----------------
    for (int idx = tid; idx < 4096; idx += 256) {
        int n = idx >> 6, c = idx & 63;
        float acc;
        if (n < 63) {
            acc = b_dev[c];
            const float* o = s_obs + n * 14;
            #pragma unroll
            for (int k = 0; k < 14; k++) acc = fmaf(o[k], s_pool[k * 64 + c], acc);
        } else {
            acc = b_srv[c];
            #pragma unroll
            for (int k = 0; k < 3; k++) acc = fmaf(s_obs[882 + k], s_pool[896 + k * 64 + c], acc);
        }
        s_a[idx] = fmaxf(acc, 0.0f);
    }
    __syncthreads();

    // ---------------- Phase 3: 3 GCN layers ----------------
    float* s_t = s_pool;          // aggregation result (4096)
    float* s_w = s_pool + 4096;   // layer weight (4096)

    const float* Ws[3] = {W1, W2, W3};
    const float* bs[3] = {b1, b2, b3};

    #pragma unroll 1
    for (int L = 0; L < 3; L++) {
        // stage W, scale input rows by dinv[j]
        for (int i = tid; i < 4096; i += 256) s_w[i] = Ws[L][i];
        for (int idx = tid; idx < 4096; idx += 256) s_a[idx] *= s_dinv[idx >> 6];
        __syncthreads();

        // sparse aggregation: t[r][c] = dinv[r] * sum_{j in mask_r} (dinv[j]*x[j][c])
        for (int r = warp; r < 64; r += 8) {
            unsigned m0 = s_mlo[r], m1 = s_mhi[r];
            float a0 = 0.0f, a1 = 0.0f;
            while (m0) {
                int j = __ffs(m0) - 1; m0 &= m0 - 1;
                a0 += s_a[j * 64 + lane];
                a1 += s_a[j * 64 + 32 + lane];
            }
            while (m1) {
                int j = __ffs(m1) + 31; m1 &= m1 - 1;
                a0 += s_a[j * 64 + lane];
                a1 += s_a[j * 64 + 32 + lane];
            }
            float di = s_dinv[r];
            s_t[r * 64 + lane]      = di * a0;
            s_t[r * 64 + 32 + lane] = di * a1;
        }
        __syncthreads();

        // h = relu(t @ W + b): thread computes 2 rows x 8 cols
        {
            const int rp = tid >> 3;        // 0..31
            const int cg = tid & 7;         // 0..7
            const int r0 = rp * 2, r1 = r0 + 1;
            const int c0 = cg * 8;
            float acc0[8] = {0,0,0,0,0,0,0,0};
            float acc1[8] = {0,0,0,0,0,0,0,0};
            #pragma unroll 8
            for (int k = 0; k < 64; k++) {
                float t0 = s_t[r0 * 64 + k];
                float t1 = s_t[r1 * 64 + k];
                float4 wA = *(const float4*)(s_w + k * 64 + c0);
                float4 wB = *(const float4*)(s_w + k * 64 + c0 + 4);
                acc0[0] = fmaf(t0, wA.x, acc0[0]); acc0[1] = fmaf(t0, wA.y, acc0[1]);
                acc0[2] = fmaf(t0, wA.z, acc0[2]); acc0[3] = fmaf(t0, wA.w, acc0[3]);
                acc0[4] = fmaf(t0, wB.x, acc0[4]); acc0[5] = fmaf(t0, wB.y, acc0[5]);
                acc0[6] = fmaf(t0, wB.z, acc0[6]); acc0[7] = fmaf(t0, wB.w, acc0[7]);
                acc1[0] = fmaf(t1, wA.x, acc1[0]); acc1[1] = fmaf(t1, wA.y, acc1[1]);
                acc1[2] = fmaf(t1, wA.z, acc1[2]); acc1[3] = fmaf(t1, wA.w, acc1[3]);
                acc1[4] = fmaf(t1, wB.x, acc1[4]); acc1[5] = fmaf(t1, wB.y, acc1[5]);
                acc1[6] = fmaf(t1, wB.z, acc1[6]); acc1[7] = fmaf(t1, wB.w, acc1[7]);
            }
            const float* bb = bs[L];
            #pragma unroll
            for (int q = 0; q < 8; q++) {
                float bias = bb[c0 + q];
                s_a[r0 * 64 + c0 + q] = fmaxf(acc0[q] + bias, 0.0f);
                s_a[r1 * 64 + c0 + q] = fmaxf(acc1[q] + bias, 0.0f);
            }
        }
        __syncthreads();
    }

    // ---------------- Phase 4: critic head ----------------
    // mean over device nodes (rows 0..62)
    if (tid < 64) {
        float s = 0.0f;
        for (int i = 0; i < 63; i++) s += s_a[i * 64 + tid];
        s_mean[tid] = s * (1.0f / 63.0f);
    }
    __syncthreads();

    // u[m] = bf1[m] + Wf1_mean^T mean + Wf1_srv^T h63  (constant over nodes)
    // concurrently: threads >=128 stage Wf1_dev (first 64x128 block) + Wf2 into SMEM
    if (tid < 128) {
        float acc = bf1[tid];
        #pragma unroll 4
        for (int k = 0; k < 64; k++) acc = fmaf(s_mean[k],        Wf1[(64  + k) * 128 + tid], acc);
        #pragma unroll 4
        for (int k = 0; k < 64; k++) acc = fmaf(s_a[63 * 64 + k], Wf1[(128 + k) * 128 + tid], acc);
        s_u[tid] = acc;
    } else {
        for (int i = tid - 128; i < 8192; i += 128) s_pool[i] = Wf1[i];
        if (tid - 128 < 128) s_wf2[tid - 128] = Wf2[tid - 128];
    }
    __syncthreads();

    // z_i = h_i @ Wf1_dev + u ; out_i = relu(z_i).Wf2 + bf2
    // thread computes 2 rows x 16 cols of z in registers, then partial dot + shfl reduce
    {
        const int rp = tid >> 3;        // 0..31 -> rows 2rp, 2rp+1
        const int cg = tid & 7;         // 0..7  -> cols 16*cg..+15
        const int r0 = rp * 2, r1 = r0 + 1;
        const int c0 = cg * 16;
        float z0[16], z1[16];
        #pragma unroll
        for (int q = 0; q < 16; q++) { z0[q] = 0.0f; z1[q] = 0.0f; }

        #pragma unroll 4
        for (int k = 0; k < 64; k++) {
            float h0 = s_a[r0 * 64 + k];
            float h1 = s_a[r1 * 64 + k];
            #pragma unroll
            for (int q = 0; q < 4; q++) {
                float4 w = *(const float4*)(s_pool + k * 128 + c0 + q * 4);
                z0[q*4+0] = fmaf(h0, w.x, z0[q*4+0]);
                z0[q*4+1] = fmaf(h0, w.y, z0[q*4+1]);
                z0[q*4+2] = fmaf(h0, w.z, z0[q*4+2]);
                z0[q*4+3] = fmaf(h0, w.w, z0[q*4+3]);
                z1[q*4+0] = fmaf(h1, w.x, z1[q*4+0]);
                z1[q*4+1] = fmaf(h1, w.y, z1[q*4+1]);
                z1[q*4+2] = fmaf(h1, w.z, z1[q*4+2]);
                z1[q*4+3] = fmaf(h1, w.w, z1[q*4+3]);
            }
        }

        float p0 = 0.0f, p1 = 0.0f;
        #pragma unroll
        for (int q = 0; q < 16; q++) {
            float uu = s_u[c0 + q];
            float wf = s_wf2[c0 + q];
            p0 = fmaf(fmaxf(z0[q] + uu, 0.0f), wf, p0);
            p1 = fmaf(fmaxf(z1[q] + uu, 0.0f), wf, p1);
        }
        // reduce over the 8-lane column groups (lanes sharing rp)
        #pragma unroll
        for (int off = 1; off < 8; off <<= 1) {
            p0 += __shfl_xor_sync(FULLMASK, p0, off);
            p1 += __shfl_xor_sync(FULLMASK, p1, off);
        }
        if (cg == 0) {
            float bias = bf2[0];
            if (r0 < 63) out[(size_t)b * 63 + r0] = p0 + bias;
            if (r1 < 63) out[(size_t)b * 63 + r1] = p1 + bias;
        }
    }
}

extern "C" void kernel_launch(void* const* d_in, const int* in_sizes, int n_in,
                              void* d_out, int out_size)
{
    (void)in_sizes; (void)n_in; (void)out_size;
    pgcn_kernel<<<16384, 256>>>(
        (const float*)d_in[0],  // device_obs
        (const float*)d_in[1],  // server_obs
        (const float*)d_in[2],  // adjacency
        (const float*)d_in[3],  // W_dev
        (const float*)d_in[4],  // b_dev
        (const float*)d_in[5],  // W_srv
        (const float*)d_in[6],  // b_srv
        (const float*)d_in[7],  // W1
        (const float*)d_in[8],  // b1
        (const float*)d_in[9],  // W2
        (const float*)d_in[10], // b2
        (const float*)d_in[11], // W3
        (const float*)d_in[12], // b3
        (const float*)d_in[13], // Wf1
        (const float*)d_in[14], // bf1
        (const float*)d_in[15], // Wf2
        (const float*)d_in[16], // bf2
        (float*)d_out);
}

// round 4
// speedup vs baseline: 1.7166x; 1.7166x over previous
#include <cuda_runtime.h>

#define FULLMASK 0xffffffffu
#define XS 68   // padded row stride (floats): 16B-aligned, bank-rotating (68 mod 32 = 4)

__global__ __launch_bounds__(256, 4)
void pgcn_kernel(
    const float* __restrict__ dev_obs, const float* __restrict__ srv_obs,
    const float* __restrict__ adj,
    const float* __restrict__ W_dev, const float* __restrict__ b_dev,
    const float* __restrict__ W_srv, const float* __restrict__ b_srv,
    const float* __restrict__ W1, const float* __restrict__ b1,
    const float* __restrict__ W2, const float* __restrict__ b2,
    const float* __restrict__ W3, const float* __restrict__ b3,
    const float* __restrict__ Wf1, const float* __restrict__ bf1,
    const float* __restrict__ Wf2, const float* __restrict__ bf2,
    float* __restrict__ out)
{
    __shared__ __align__(16) float s_a[64 * XS];     // node features (padded rows)
    __shared__ __align__(16) float s_pool[4352 + 4096]; // [t(64*XS) | W(64*64)]; head: Wf1_dev(64x128)
    __shared__ float s_obs[896];
    __shared__ unsigned s_mlo[64], s_mhi[64];
    __shared__ float s_dinv[64];
    __shared__ float s_mean[64];
    __shared__ float s_u[128];
    __shared__ float s_wf2[128];

    const int b    = blockIdx.x;
    const int tid  = threadIdx.x;
    const int lane = tid & 31;
    const int warp = tid >> 5;

    // ---- Phase 1: stage inputs, adjacency masks, dinv ----
    for (int i = tid; i < 882; i += 256) s_obs[i] = dev_obs[b * 882 + i];
    if (tid < 3) s_obs[882 + tid] = srv_obs[b * 3 + tid];
    for (int i = tid; i < 896; i += 256) s_pool[i] = W_dev[i];
    if (tid < 192) s_pool[896 + tid] = W_srv[tid];
    {
        const float* arow = adj + (size_t)b * 4096;
        for (int r = warp; r < 64; r += 8) {
            unsigned m0 = __ballot_sync(FULLMASK, arow[r * 64 + lane] != 0.0f);
            unsigned m1 = __ballot_sync(FULLMASK, arow[r * 64 + 32 + lane] != 0.0f);
            if (lane == 0) {
                s_mlo[r] = m0; s_mhi[r] = m1;
                s_dinv[r] = rsqrtf(fmaxf((float)(__popc(m0) + __popc(m1)), 1.0f));
            }
        }
    }
    __syncthreads();

    // ---- Phase 2: embedding -> s_a, pre-scaled by dinv[n] (feeds layer-1 aggregation) ----
    for (int idx = tid; idx < 4096; idx += 256) {
        int n = idx >> 6, c = idx & 63;
        float acc;
        if (n < 63) {
            acc = b_dev[c];
            const float* o = s_obs + n * 14;
            #pragma unroll
            for (int k = 0; k < 14; k++) acc = fmaf(o[k], s_pool[k * 64 + c], acc);
        } else {
            acc = b_srv[c];
            #pragma unroll
            for (int k = 0; k < 3; k++) acc = fmaf(s_obs[882 + k], s_pool[896 + k * 64 + c], acc);
        }
        s_a[n * XS + c] = fmaxf(acc, 0.0f) * s_dinv[n];
    }
    __syncthreads();

    // ---- Phase 3: 3 GCN layers ----
    float* s_t = s_pool;            // 64*XS
    float* s_w = s_pool + 64 * XS;  // 64*64

    const float* Ws[3] = {W1, W2, W3};
    const float* bs[3] = {b1, b2, b3};

    #pragma unroll 1
    for (int L = 0; L < 3; L++) {
        for (int i = tid; i < 4096; i += 256) s_w[i] = Ws[L][i];
        __syncthreads();

        // sparse aggregation: t[r] = dinv[r] * sum_{j in mask_r} s_a[j]   (s_a pre-scaled)
        for (int r = warp; r < 64; r += 8) {
            unsigned m0 = s_mlo[r], m1 = s_mhi[r];
            float a0 = 0.0f, a1 = 0.0f;
            while (m0) {
                int j = __ffs(m0) - 1; m0 &= m0 - 1;
                a0 += s_a[j * XS + lane]; a1 += s_a[j * XS + 32 + lane];
            }
            while (m1) {
                int j = __ffs(m1) + 31; m1 &= m1 - 1;
                a0 += s_a[j * XS + lane]; a1 += s_a[j * XS + 32 + lane];
            }
            float di = s_dinv[r];
            s_t[r * XS + lane] = di * a0; s_t[r * XS + 32 + lane] = di * a1;
        }
        __syncthreads();

        // h = relu(t @ W + b), pre-scaled by dinv for next agg (except last layer).
        // thread: rows {2rp, 2rp+1}, cols {cg*4 + 32q + j} -> warp LDS.128 is 128B-contiguous.
        {
            const int rp = tid >> 3, cg = tid & 7;
            const int r0 = rp * 2, r1 = r0 + 1, cbase = cg * 4;
            float acc0[8] = {0,0,0,0,0,0,0,0}, acc1[8] = {0,0,0,0,0,0,0,0};
            #pragma unroll 8
            for (int k = 0; k < 64; k++) {
                float t0 = s_t[r0 * XS + k];
                float t1 = s_t[r1 * XS + k];
                float4 wA = *(const float4*)(s_w + k * 64 + cbase);       // cols cbase..+3
                float4 wB = *(const float4*)(s_w + k * 64 + cbase + 32);  // cols cbase+32..+35
                acc0[0] = fmaf(t0, wA.x, acc0[0]); acc0[1] = fmaf(t0, wA.y, acc0[1]);
                acc0[2] = fmaf(t0, wA.z, acc0[2]); acc0[3] = fmaf(t0, wA.w, acc0[3]);
                acc0[4] = fmaf(t0, wB.x, acc0[4]); acc0[5] = fmaf(t0, wB.y, acc0[5]);
                acc0[6] = fmaf(t0, wB.z, acc0[6]); acc0[7] = fmaf(t0, wB.w, acc0[7]);
                acc1[0] = fmaf(t1, wA.x, acc1[0]); acc1[1] = fmaf(t1, wA.y, acc1[1]);
                acc1[2] = fmaf(t1, wA.z, acc1[2]); acc1[3] = fmaf(t1, wA.w, acc1[3]);
                acc1[4] = fmaf(t1, wB.x, acc1[4]); acc1[5] = fmaf(t1, wB.y, acc1[5]);
                acc1[6] = fmaf(t1, wB.z, acc1[6]); acc1[7] = fmaf(t1, wB.w, acc1[7]);
            }
            const float* bb = bs[L];
            float sc0 = (L < 2) ? s_dinv[r0] : 1.0f;
            float sc1 = (L < 2) ? s_dinv[r1] : 1.0f;
            #pragma unroll
            for (int q = 0; q < 8; q++) {
                int c = cbase + (q >> 2) * 32 + (q & 3);
                float bias = bb[c];
                s_a[r0 * XS + c] = fmaxf(acc0[q] + bias, 0.0f) * sc0;
                s_a[r1 * XS + c] = fmaxf(acc1[q] + bias, 0.0f) * sc1;
            }
        }
        __syncthreads();
    }

    // ---- Phase 4: head ----
    if (tid < 64) {
        float s = 0.0f;
        for (int i = 0; i < 63; i++) s += s_a[i * XS + tid];
        s_mean[tid] = s * (1.0f / 63.0f);
    }
    __syncthreads();

    if (tid < 128) {
        float acc = bf1[tid];
        #pragma unroll 4
        for (int k = 0; k < 64; k++) acc = fmaf(s_mean[k],        Wf1[(64  + k) * 128 + tid], acc);
        #pragma unroll 4
        for (int k = 0; k < 64; k++) acc = fmaf(s_a[63 * XS + k], Wf1[(128 + k) * 128 + tid], acc);
        s_u[tid] = acc;
    } else {
        for (int i = tid - 128; i < 8192; i += 128) s_pool[i] = Wf1[i];
        if (tid - 128 < 128) s_wf2[tid - 128] = Wf2[tid - 128];
    }
    __syncthreads();

    // z_i = h_i @ Wf1_dev + u; out = relu(z).Wf2 + bf2
    // thread: rows {2rp,2rp+1}, cols {cg*4 + 32q + j}, q=0..3
    {
        const int rp = tid >> 3, cg = tid & 7;
        const int r0 = rp * 2, r1 = r0 + 1, cbase = cg * 4;
        float z0[16], z1[16];
        #pragma unroll
        for (int q = 0; q < 16; q++) { z0[q] = 0.0f; z1[q] = 0.0f; }

        #pragma unroll 4
        for (int k = 0; k < 64; k++) {
            float h0 = s_a[r0 * XS + k];
            float h1 = s_a[r1 * XS + k];
            #pragma unroll
            for (int q = 0; q < 4; q++) {
                float4 w = *(const float4*)(s_pool + k * 128 + cbase + q * 32);
                z0[q*4+0] = fmaf(h0, w.x, z0[q*4+0]); z0[q*4+1] = fmaf(h0, w.y, z0[q*4+1]);
                z0[q*4+2] = fmaf(h0, w.z, z0[q*4+2]); z0[q*4+3] = fmaf(h0, w.w, z0[q*4+3]);
                z1[q*4+0] = fmaf(h1, w.x, z1[q*4+0]); z1[q*4+1] = fmaf(h1, w.y, z1[q*4+1]);
                z1[q*4+2] = fmaf(h1, w.z, z1[q*4+2]); z1[q*4+3] = fmaf(h1, w.w, z1[q*4+3]);
            }
        }

        float p0 = 0.0f, p1 = 0.0f;
        #pragma unroll
        for (int q = 0; q < 16; q++) {
            int c = cbase + (q >> 2) * 32 + (q & 3);
            float uu = s_u[c], wf = s_wf2[c];
            p0 = fmaf(fmaxf(z0[q] + uu, 0.0f), wf, p0);
            p1 = fmaf(fmaxf(z1[q] + uu, 0.0f), wf, p1);
        }
        #pragma unroll
        for (int off = 1; off < 8; off <<= 1) {
            p0 += __shfl_xor_sync(FULLMASK, p0, off);
            p1 += __shfl_xor_sync(FULLMASK, p1, off);
        }
        if (cg == 0) {
            float bias = bf2[0];
            if (r0 < 63) out[(size_t)b * 63 + r0] = p0 + bias;
            if (r1 < 63) out[(size_t)b * 63 + r1] = p1 + bias;
        }
    }
}

extern "C" void kernel_launch(void* const* d_in, const int* in_sizes, int n_in,
                              void* d_out, int out_size)
{
    (void)in_sizes; (void)n_in; (void)out_size;
    pgcn_kernel<<<16384, 256>>>(
        (const float*)d_in[0],  (const float*)d_in[1],  (const float*)d_in[2],
        (const float*)d_in[3],  (const float*)d_in[4],  (const float*)d_in[5],
        (const float*)d_in[6],  (const float*)d_in[7],  (const float*)d_in[8],
        (const float*)d_in[9],  (const float*)d_in[10], (const float*)d_in[11],
        (const float*)d_in[12], (const float*)d_in[13], (const float*)d_in[14],
        (const float*)d_in[15], (const float*)d_in[16], (float*)d_out);
}

// round 6
// speedup vs baseline: 2.8264x; 1.6465x over previous
#include <cuda_runtime.h>
#include <cuda_bf16.h>
#include <cstdint>

#define ST 144                      // row stride in bytes (72 bf16) — bank-rotating, 16B-aligned
#define ADJ_O   0                   // adjacency / h3_hi  (64 rows)
#define XTH_O   9216                // X^T hi / h3_lo
#define XTL_O   18432               // X^T lo
#define TH_O    27648               // T hi   (obs scratch pre-loop)
#define TL_O    36864               // T lo
#define WH_O    46080               // W^T hi (128 rows capacity; embW scratch pre-loop)
#define WL_O    64512               // W^T lo
#define MLO_O   82944
#define MHI_O   83200
#define DINV_O  83456
#define BIAS_O  83712
#define U_O     83968
#define WF2_O   84480
#define MEAN_O  84992
#define H3S_O   85248
#define PART_O  85504               // float[2][64]
#define SMEM_BYTES 86032

static __device__ __align__(16) unsigned char g_WT[3][2][9216];   // W_L^T [n][k] hi/lo
static __device__ __align__(16) unsigned char g_Wf1T[2][18432];   // Wf1_dev^T [m][k] hi/lo

__device__ __forceinline__ uint32_t smem_u32(const void* p) {
    uint32_t a;
    asm("{ .reg .u64 t; cvta.to.shared.u64 t, %1; cvt.u32.u64 %0, t; }" : "=r"(a) : "l"(p));
    return a;
}
__device__ __forceinline__ void ldsm4(uint32_t addr, uint32_t* r) {
    asm volatile("ldmatrix.sync.aligned.m8n8.x4.shared.b16 {%0,%1,%2,%3}, [%4];"
                 : "=r"(r[0]), "=r"(r[1]), "=r"(r[2]), "=r"(r[3]) : "r"(addr));
}
__device__ __forceinline__ void mma16816(float* d, const uint32_t* a, const uint32_t* b) {
    asm volatile("mma.sync.aligned.m16n8k16.row.col.f32.bf16.bf16.f32 "
        "{%0,%1,%2,%3}, {%4,%5,%6,%7}, {%8,%9}, {%0,%1,%2,%3};"
        : "+f"(d[0]), "+f"(d[1]), "+f"(d[2]), "+f"(d[3])
        : "r"(a[0]), "r"(a[1]), "r"(a[2]), "r"(a[3]), "r"(b[0]), "r"(b[1]));
}
__device__ __forceinline__ void sp1(float v, uint16_t& h, uint16_t& l) {
    __nv_bfloat16 hb = __float2bfloat16(v);
    __nv_bfloat16 lb = __float2bfloat16(v - __bfloat162float(hb));
    h = __bfloat16_as_ushort(hb); l = __bfloat16_as_ushort(lb);
}
__device__ __forceinline__ uint32_t sp2(float a, float b, uint32_t& lo) {
    uint16_t ah, al, bh, bl; sp1(a, ah, al); sp1(b, bh, bl);
    lo = (uint32_t)al | ((uint32_t)bl << 16);
    return (uint32_t)ah | ((uint32_t)bh << 16);
}
__device__ __forceinline__ float rdbf(const unsigned char* sm, int off, int r, int c) {
    return __bfloat162float(*(const __nv_bfloat16*)(sm + off + r * ST + c * 2));
}
// one K=64 product: D(16x32) += A_img[m0..][k] @ B_img[n0..][k]^T ; acc = 4 n-tiles x 4
__device__ __forceinline__ void gprod(uint32_t aB, uint32_t bB, int lane, float (*acc)[4]) {
    const int arow = lane & 15, acol = (lane >> 4) << 3;
    const int brow = (lane & 7) + ((lane & 16) >> 1), bcol = lane & 8;
    #pragma unroll
    for (int kk = 0; kk < 64; kk += 16) {
        uint32_t a[4]; ldsm4(aB + arow * ST + (kk + acol) * 2, a);
        #pragma unroll
        for (int nt = 0; nt < 2; nt++) {
            uint32_t bf[4]; ldsm4(bB + (nt * 16 + brow) * ST + (kk + bcol) * 2, bf);
            mma16816(acc[nt * 2], a, bf);
            mma16816(acc[nt * 2 + 1], a, bf + 2);
        }
    }
}

__global__ void pgcn_prep(const float* __restrict__ W1, const float* __restrict__ W2,
                          const float* __restrict__ W3, const float* __restrict__ Wf1) {
    const float* Ws[3] = {W1, W2, W3};
    int gt = blockIdx.x * blockDim.x + threadIdx.x, nth = gridDim.x * blockDim.x;
    for (int L = 0; L < 3; L++)
        for (int i = gt; i < 4096; i += nth) {
            int n = i >> 6, k = i & 63;
            uint16_t h, l; sp1(Ws[L][k * 64 + n], h, l);
            *(uint16_t*)(g_WT[L][0] + n * ST + k * 2) = h;
            *(uint16_t*)(g_WT[L][1] + n * ST + k * 2) = l;
        }
    for (int i = gt; i < 8192; i += nth) {
        int m = i >> 6, k = i & 63;
        uint16_t h, l; sp1(Wf1[k * 128 + m], h, l);
        *(uint16_t*)(g_Wf1T[0] + m * ST + k * 2) = h;
        *(uint16_t*)(g_Wf1T[1] + m * ST + k * 2) = l;
    }
}

__global__ __launch_bounds__(256)
void pgcn_main(const float* __restrict__ dev_obs, const float* __restrict__ srv_obs,
               const float* __restrict__ adj,
               const float* __restrict__ W_dev, const float* __restrict__ b_dev,
               const float* __restrict__ W_srv, const float* __restrict__ b_srv,
               const float* __restrict__ b1, const float* __restrict__ b2,
               const float* __restrict__ b3,
               const float* __restrict__ Wf1, const float* __restrict__ bf1,
               const float* __restrict__ Wf2, const float* __restrict__ bf2,
               float* __restrict__ out)
{
    extern __shared__ __align__(16) unsigned char sm[];
    const uint32_t sb = smem_u32(sm);
    unsigned* s_mlo = (unsigned*)(sm + MLO_O);
    unsigned* s_mhi = (unsigned*)(sm + MHI_O);
    float* s_dinv = (float*)(sm + DINV_O);
    float* s_bias = (float*)(sm + BIAS_O);
    float* s_u    = (float*)(sm + U_O);
    float* s_wf2  = (float*)(sm + WF2_O);
    float* s_mean = (float*)(sm + MEAN_O);
    float* s_h3s  = (float*)(sm + H3S_O);
    float* s_part = (float*)(sm + PART_O);

    const int tid = threadIdx.x, lane = tid & 31, wid = tid >> 5;
    const int b = blockIdx.x;
    const int m0 = (wid & 3) * 16, ch2 = wid >> 2, n0 = ch2 * 32;
    const int g = lane >> 2, c0b = (lane & 3) * 2;

    // ---- stage obs + emb weights (scratch in T/W regions), masks + dinv ----
    float* s_obs = (float*)(sm + TH_O);
    float* s_ew  = (float*)(sm + WH_O);
    for (int i = tid; i < 882; i += 256) s_obs[i] = dev_obs[(size_t)b * 882 + i];
    if (tid < 3) s_obs[882 + tid] = srv_obs[b * 3 + tid];
    for (int i = tid; i < 896; i += 256) s_ew[i] = W_dev[i];
    if (tid < 192) s_ew[896 + tid] = W_srv[tid];
    {
        const float* ar = adj + (size_t)b * 4096;
        for (int r = wid; r < 64; r += 8) {
            unsigned a0 = __ballot_sync(0xffffffffu, ar[r * 64 + lane] != 0.0f);
            unsigned a1 = __ballot_sync(0xffffffffu, ar[r * 64 + 32 + lane] != 0.0f);
            if (lane == 0) {
                s_mlo[r] = a0; s_mhi[r] = a1;
                s_dinv[r] = rsqrtf(fmaxf((float)(__popc(a0) + __popc(a1)), 1.0f));
            }
        }
    }
    __syncthreads();

    // ---- adjacency bf16 [r][j] + embedding -> X^T [c][n]*dinv[n] (hi/lo) ----
    for (int i = tid; i < 512; i += 256) {
        int r = i >> 3, chk = i & 7;
        unsigned byte8 = ((chk < 4 ? s_mlo[r] : s_mhi[r]) >> ((chk & 3) * 8)) & 0xFF;
        uint4 v; uint32_t* vp = (uint32_t*)&v;
        #pragma unroll
        for (int j = 0; j < 4; j++) {
            unsigned b2 = (byte8 >> (2 * j)) & 3;
            vp[j] = ((b2 & 1) ? 0x3F80u : 0u) | ((b2 & 2) ? 0x3F800000u : 0u);
        }
        *(uint4*)(sm + ADJ_O + r * ST + chk * 16) = v;
    }
    for (int it = 0; it < 8; it++) {
        int idx = tid + it * 256, c = idx & 63, nn0 = (idx >> 6) * 2;
        float e[2];
        #pragma unroll
        for (int q = 0; q < 2; q++) {
            int n = nn0 + q; float acc;
            if (n < 63) {
                acc = b_dev[c];
                const float* o = s_obs + n * 14;
                #pragma unroll
                for (int k = 0; k < 14; k++) acc = fmaf(o[k], s_ew[k * 64 + c], acc);
            } else {
                acc = b_srv[c];
                #pragma unroll
                for (int k = 0; k < 3; k++) acc = fmaf(s_obs[882 + k], s_ew[896 + k * 64 + c], acc);
            }
            e[q] = fmaxf(acc, 0.0f) * s_dinv[n];
        }
        uint32_t lo, hi = sp2(e[0], e[1], lo);
        *(uint32_t*)(sm + XTH_O + c * ST + nn0 * 2) = hi;
        *(uint32_t*)(sm + XTL_O + c * ST + nn0 * 2) = lo;
    }
    __syncthreads();

    // ---- 3 GCN layers ----
    #pragma unroll 1
    for (int L = 0; L < 3; L++) {
        {   // stage W^T hi/lo + bias (W region free: prior readers past last sync)
            const uint4* wh = (const uint4*)g_WT[L][0];
            const uint4* wl = (const uint4*)g_WT[L][1];
            for (int i = tid; i < 576; i += 256) {
                ((uint4*)(sm + WH_O))[i] = wh[i];
                ((uint4*)(sm + WL_O))[i] = wl[i];
            }
            const float* bl = (L == 0) ? b1 : (L == 1) ? b2 : b3;
            if (tid < 64) s_bias[tid] = bl[tid];
        }
        // aggregation: D = Adj @ X^T(hi)ᵀ + Adj @ X^T(lo)ᵀ
        float acc[4][4];
        #pragma unroll
        for (int i = 0; i < 4; i++) { acc[i][0]=acc[i][1]=acc[i][2]=acc[i][3]=0.f; }
        gprod(sb + ADJ_O + m0 * ST, sb + XTH_O + n0 * ST, lane, acc);
        gprod(sb + ADJ_O + m0 * ST, sb + XTL_O + n0 * ST, lane, acc);
        __syncthreads();   // W staged; all XT/Adj reads done

        // epi1: T[r][c] = dinv[r]*D  -> TH/TL
        const int r0 = m0 + g, r1 = r0 + 8;
        float d0 = s_dinv[r0], d1 = s_dinv[r1];
        #pragma unroll
        for (int nt = 0; nt < 4; nt++) {
            int c0 = n0 + nt * 8 + c0b;
            uint32_t lo, hi;
            hi = sp2(acc[nt][0] * d0, acc[nt][1] * d0, lo);
            *(uint32_t*)(sm + TH_O + r0 * ST + c0 * 2) = hi;
            *(uint32_t*)(sm + TL_O + r0 * ST + c0 * 2) = lo;
            hi = sp2(acc[nt][2] * d1, acc[nt][3] * d1, lo);
            *(uint32_t*)(sm + TH_O + r1 * ST + c0 * 2) = hi;
            *(uint32_t*)(sm + TL_O + r1 * ST + c0 * 2) = lo;
        }
        __syncthreads();   // T visible

        // layer GEMM: D = T@W = Thi·Whi + Tlo·Whi + Thi·Wlo
        #pragma unroll
        for (int i = 0; i < 4; i++) { acc[i][0]=acc[i][1]=acc[i][2]=acc[i][3]=0.f; }
        gprod(sb + TH_O + m0 * ST, sb + WH_O + n0 * ST, lane, acc);
        gprod(sb + TL_O + m0 * ST, sb + WH_O + n0 * ST, lane, acc);
        gprod(sb + TH_O + m0 * ST, sb + WL_O + n0 * ST, lane, acc);

        if (L < 2) {
            // epi2: X^T_next[c][r] = relu(D+b[c])*dinv[r]  (transposed scatter)
            #pragma unroll
            for (int nt = 0; nt < 4; nt++) {
                int c0 = n0 + nt * 8 + c0b;
                float v00 = fmaxf(acc[nt][0] + s_bias[c0],     0.f) * d0;
                float v01 = fmaxf(acc[nt][1] + s_bias[c0 + 1], 0.f) * d0;
                float v10 = fmaxf(acc[nt][2] + s_bias[c0],     0.f) * d1;
                float v11 = fmaxf(acc[nt][3] + s_bias[c0 + 1], 0.f) * d1;
                uint16_t h, l;
                sp1(v00, h, l);
                *(uint16_t*)(sm + XTH_O + c0 * ST + r0 * 2) = h;
                *(uint16_t*)(sm + XTL_O + c0 * ST + r0 * 2) = l;
                sp1(v01, h, l);
                *(uint16_t*)(sm + XTH_O + (c0 + 1) * ST + r0 * 2) = h;
                *(uint16_t*)(sm + XTL_O + (c0 + 1) * ST + r0 * 2) = l;
                sp1(v10, h, l);
                *(uint16_t*)(sm + XTH_O + c0 * ST + r1 * 2) = h;
                *(uint16_t*)(sm + XTL_O + c0 * ST + r1 * 2) = l;
                sp1(v11, h, l);
                *(uint16_t*)(sm + XTH_O + (c0 + 1) * ST + r1 * 2) = h;
                *(uint16_t*)(sm + XTL_O + (c0 + 1) * ST + r1 * 2) = l;
            }
        } else {
            // epi3: h3[r][c] = relu(D+b[c])  -> hi in ADJ region, lo in XTH region
            #pragma unroll
            for (int nt = 0; nt < 4; nt++) {
                int c0 = n0 + nt * 8 + c0b;
                uint32_t lo, hi;
                hi = sp2(fmaxf(acc[nt][0] + s_bias[c0], 0.f),
                         fmaxf(acc[nt][1] + s_bias[c0 + 1], 0.f), lo);
                *(uint32_t*)(sm + ADJ_O + r0 * ST + c0 * 2) = hi;
                *(uint32_t*)(sm + XTH_O + r0 * ST + c0 * 2) = lo;
                hi = sp2(fmaxf(acc[nt][2] + s_bias[c0], 0.f),
                         fmaxf(acc[nt][3] + s_bias[c0 + 1], 0.f), lo);
                *(uint32_t*)(sm + ADJ_O + r1 * ST + c0 * 2) = hi;
                *(uint32_t*)(sm + XTH_O + r1 * ST + c0 * 2) = lo;
            }
        }
        __syncthreads();
    }

    // ---- head prep: mean + server row || stage Wf1^T (128 rows hi/lo) ----
    if (tid < 64) {
        float s = 0.0f;
        for (int r = 0; r < 63; r++) s += rdbf(sm, ADJ_O, r, tid) + rdbf(sm, XTH_O, r, tid);
        s_mean[tid] = s * (1.0f / 63.0f);
        s_h3s[tid] = rdbf(sm, ADJ_O, 63, tid) + rdbf(sm, XTH_O, 63, tid);
    } else {
        const uint4* hh = (const uint4*)g_Wf1T[0];
        const uint4* hl = (const uint4*)g_Wf1T[1];
        for (int i = tid - 64; i < 1152; i += 192) {
            ((uint4*)(sm + WH_O))[i] = hh[i];
            ((uint4*)(sm + WL_O))[i] = hl[i];
        }
    }
    __syncthreads();
    if (tid < 128) {
        float acc = bf1[tid];
        #pragma unroll 4
        for (int k = 0; k < 64; k++) acc = fmaf(s_mean[k], Wf1[(64 + k) * 128 + tid], acc);
        #pragma unroll 4
        for (int k = 0; k < 64; k++) acc = fmaf(s_h3s[k], Wf1[(128 + k) * 128 + tid], acc);
        s_u[tid] = acc;
    } else if (tid < 256 && tid - 128 < 128) {
        s_wf2[tid - 128] = Wf2[tid - 128];
    }
    __syncthreads();

    // ---- head GEMM: Z(16x64 per warp) = h3 @ Wf1dev^T ----
    {
        const int n0h = ch2 * 64;
        float a8[8][4];
        #pragma unroll
        for (int i = 0; i < 8; i++) { a8[i][0]=a8[i][1]=a8[i][2]=a8[i][3]=0.f; }
        gprod(sb + ADJ_O + m0 * ST, sb + WH_O + n0h * ST,        lane, a8);
        gprod(sb + ADJ_O + m0 * ST, sb + WH_O + (n0h + 32) * ST, lane, a8 + 4);
        gprod(sb + XTH_O + m0 * ST, sb + WH_O + n0h * ST,        lane, a8);
        gprod(sb + XTH_O + m0 * ST, sb + WH_O + (n0h + 32) * ST, lane, a8 + 4);
        gprod(sb + ADJ_O + m0 * ST, sb + WL_O + n0h * ST,        lane, a8);
        gprod(sb + ADJ_O + m0 * ST, sb + WL_O + (n0h + 32) * ST, lane, a8 + 4);

        float p0 = 0.f, p1 = 0.f;
        #pragma unroll
        for (int nt = 0; nt < 8; nt++) {
            int c0 = n0h + nt * 8 + c0b;
            float u0 = s_u[c0], u1 = s_u[c0 + 1], w0 = s_wf2[c0], w1 = s_wf2[c0 + 1];
            p0 = fmaf(fmaxf(a8[nt][0] + u0, 0.f), w0, p0);
            p0 = fmaf(fmaxf(a8[nt][1] + u1, 0.f), w1, p0);
            p1 = fmaf(fmaxf(a8[nt][2] + u0, 0.f), w0, p1);
            p1 = fmaf(fmaxf(a8[nt][3] + u1, 0.f), w1, p1);
        }
        p0 += __shfl_xor_sync(0xffffffffu, p0, 1); p0 += __shfl_xor_sync(0xffffffffu, p0, 2);
        p1 += __shfl_xor_sync(0xffffffffu, p1, 1); p1 += __shfl_xor_sync(0xffffffffu, p1, 2);
        if ((lane & 3) == 0) {
            s_part[ch2 * 64 + m0 + g] = p0;
            s_part[ch2 * 64 + m0 + g + 8] = p1;
        }
    }
    __syncthreads();
    if (tid < 63) out[(size_t)b * 63 + tid] = s_part[tid] + s_part[64 + tid] + bf2[0];
}

extern "C" void kernel_launch(void* const* d_in, const int* in_sizes, int n_in,
                              void* d_out, int out_size)
{
    (void)in_sizes; (void)n_in; (void)out_size;
    cudaFuncSetAttribute(pgcn_main, cudaFuncAttributeMaxDynamicSharedMemorySize, SMEM_BYTES);
    pgcn_prep<<<64, 256>>>((const float*)d_in[7], (const float*)d_in[9],
                           (const float*)d_in[11], (const float*)d_in[13]);
    pgcn_main<<<16384, 256, SMEM_BYTES>>>(
        (const float*)d_in[0],  (const float*)d_in[1],  (const float*)d_in[2],
        (const float*)d_in[3],  (const float*)d_in[4],  (const float*)d_in[5],
        (const float*)d_in[6],  (const float*)d_in[8],  (const float*)d_in[10],
        (const float*)d_in[12], (const float*)d_in[13], (const float*)d_in[14],
        (const float*)d_in[15], (const float*)d_in[16], (float*)d_out);
}

// round 7
// speedup vs baseline: 3.9540x; 1.3989x over previous
#include <cuda_runtime.h>
#include <cuda_bf16.h>
#include <cstdint>

#define ST 144                      // row stride in bytes (72 bf16) — bank-rotating, 16B-aligned
#define ADJ_O   0                   // adjacency / h3_hi  (64 rows)
#define XTH_O   9216                // X^T hi / h3_lo
#define XTL_O   18432               // X^T lo
#define TH_O    27648               // T hi   (obs scratch pre-loop; head: Wf1^T hi rows 64-127)
#define TL_O    36864               // T lo   (head: Wf1^T lo rows 64-127)
#define WH_O    46080               // W^T hi (embW scratch pre-loop; head: Wf1^T hi rows 0-63)
#define WL_O    55296               // W^T lo (head: Wf1^T lo rows 0-63)
#define MLO_O   64512
#define MHI_O   64768
#define DINV_O  65024
#define BIAS_O  65280
#define U_O     65536
#define WF2_O   66048
#define MEAN_O  66560
#define H3S_O   66816
#define PART_O  67072               // float[2][64]
#define SMEM_BYTES 67584

static __device__ __align__(16) unsigned char g_WT[3][2][9216];   // W_L^T [n][k] hi/lo
static __device__ __align__(16) unsigned char g_Wf1T[2][18432];   // Wf1_dev^T [m][k] hi/lo

__device__ __forceinline__ uint32_t smem_u32(const void* p) {
    uint32_t a;
    asm("{ .reg .u64 t; cvta.to.shared.u64 t, %1; cvt.u32.u64 %0, t; }" : "=r"(a) : "l"(p));
    return a;
}
__device__ __forceinline__ void ldsm4(uint32_t addr, uint32_t* r) {
    asm volatile("ldmatrix.sync.aligned.m8n8.x4.shared.b16 {%0,%1,%2,%3}, [%4];"
                 : "=r"(r[0]), "=r"(r[1]), "=r"(r[2]), "=r"(r[3]) : "r"(addr));
}
__device__ __forceinline__ void mma16816(float* d, const uint32_t* a, const uint32_t* b) {
    asm volatile("mma.sync.aligned.m16n8k16.row.col.f32.bf16.bf16.f32 "
        "{%0,%1,%2,%3}, {%4,%5,%6,%7}, {%8,%9}, {%0,%1,%2,%3};"
        : "+f"(d[0]), "+f"(d[1]), "+f"(d[2]), "+f"(d[3])
        : "r"(a[0]), "r"(a[1]), "r"(a[2]), "r"(a[3]), "r"(b[0]), "r"(b[1]));
}
__device__ __forceinline__ void sp1(float v, uint16_t& h, uint16_t& l) {
    __nv_bfloat16 hb = __float2bfloat16(v);
    __nv_bfloat16 lb = __float2bfloat16(v - __bfloat162float(hb));
    h = __bfloat16_as_ushort(hb); l = __bfloat16_as_ushort(lb);
}
__device__ __forceinline__ uint32_t sp2(float a, float b, uint32_t& lo) {
    uint16_t ah, al, bh, bl; sp1(a, ah, al); sp1(b, bh, bl);
    lo = (uint32_t)al | ((uint32_t)bl << 16);
    return (uint32_t)ah | ((uint32_t)bh << 16);
}
__device__ __forceinline__ float rdbf(const unsigned char* sm, int off, int r, int c) {
    return __bfloat162float(*(const __nv_bfloat16*)(sm + off + r * ST + c * 2));
}
// one K=64 product: D(16x32) += A_img[m0..][k] @ B_img[n0..][k]^T ; acc = 4 n-tiles x 4
__device__ __forceinline__ void gprod(uint32_t aB, uint32_t bB, int lane, float (*acc)[4]) {
    const int arow = lane & 15, acol = (lane >> 4) << 3;
    const int brow = (lane & 7) + ((lane & 16) >> 1), bcol = lane & 8;
    #pragma unroll
    for (int kk = 0; kk < 64; kk += 16) {
        uint32_t a[4]; ldsm4(aB + arow * ST + (kk + acol) * 2, a);
        #pragma unroll
        for (int nt = 0; nt < 2; nt++) {
            uint32_t bf[4]; ldsm4(bB + (nt * 16 + brow) * ST + (kk + bcol) * 2, bf);
            mma16816(acc[nt * 2], a, bf);
            mma16816(acc[nt * 2 + 1], a, bf + 2);
        }
    }
}

__global__ void pgcn_prep(const float* __restrict__ W1, const float* __restrict__ W2,
                          const float* __restrict__ W3, const float* __restrict__ Wf1) {
    const float* Ws[3] = {W1, W2, W3};
    int gt = blockIdx.x * blockDim.x + threadIdx.x, nth = gridDim.x * blockDim.x;
    for (int L = 0; L < 3; L++)
        for (int i = gt; i < 4096; i += nth) {
            int n = i >> 6, k = i & 63;
            uint16_t h, l; sp1(Ws[L][k * 64 + n], h, l);
            *(uint16_t*)(g_WT[L][0] + n * ST + k * 2) = h;
            *(uint16_t*)(g_WT[L][1] + n * ST + k * 2) = l;
        }
    for (int i = gt; i < 8192; i += nth) {
        int m = i >> 6, k = i & 63;
        uint16_t h, l; sp1(Wf1[k * 128 + m], h, l);
        *(uint16_t*)(g_Wf1T[0] + m * ST + k * 2) = h;
        *(uint16_t*)(g_Wf1T[1] + m * ST + k * 2) = l;
    }
}

__global__ __launch_bounds__(256, 3)
void pgcn_main(const float* __restrict__ dev_obs, const float* __restrict__ srv_obs,
               const float* __restrict__ adj,
               const float* __restrict__ W_dev, const float* __restrict__ b_dev,
               const float* __restrict__ W_srv, const float* __restrict__ b_srv,
               const float* __restrict__ b1, const float* __restrict__ b2,
               const float* __restrict__ b3,
               const float* __restrict__ Wf1, const float* __restrict__ bf1,
               const float* __restrict__ Wf2, const float* __restrict__ bf2,
               float* __restrict__ out)
{
    extern __shared__ __align__(16) unsigned char sm[];
    const uint32_t sb = smem_u32(sm);
    unsigned* s_mlo = (unsigned*)(sm + MLO_O);
    unsigned* s_mhi = (unsigned*)(sm + MHI_O);
    float* s_dinv = (float*)(sm + DINV_O);
    float* s_bias = (float*)(sm + BIAS_O);
    float* s_u    = (float*)(sm + U_O);
    float* s_wf2  = (float*)(sm + WF2_O);
    float* s_mean = (float*)(sm + MEAN_O);
    float* s_h3s  = (float*)(sm + H3S_O);
    float* s_part = (float*)(sm + PART_O);

    const int tid = threadIdx.x, lane = tid & 31, wid = tid >> 5;
    const int b = blockIdx.x;
    const int m0 = (wid & 3) * 16, ch2 = wid >> 2, n0 = ch2 * 32;
    const int g = lane >> 2, c0b = (lane & 3) * 2;

    // ---- stage obs + emb weights (scratch in T/W regions), masks + dinv ----
    float* s_obs = (float*)(sm + TH_O);
    float* s_ew  = (float*)(sm + WH_O);
    for (int i = tid; i < 882; i += 256) s_obs[i] = dev_obs[(size_t)b * 882 + i];
    if (tid < 3) s_obs[882 + tid] = srv_obs[b * 3 + tid];
    for (int i = tid; i < 896; i += 256) s_ew[i] = W_dev[i];
    if (tid < 192) s_ew[896 + tid] = W_srv[tid];
    {
        const float* ar = adj + (size_t)b * 4096;
        for (int r = wid; r < 64; r += 8) {
            unsigned a0 = __ballot_sync(0xffffffffu, ar[r * 64 + lane] != 0.0f);
            unsigned a1 = __ballot_sync(0xffffffffu, ar[r * 64 + 32 + lane] != 0.0f);
            if (lane == 0) {
                s_mlo[r] = a0; s_mhi[r] = a1;
                s_dinv[r] = rsqrtf(fmaxf((float)(__popc(a0) + __popc(a1)), 1.0f));
            }
        }
    }
    __syncthreads();

    // ---- adjacency bf16 [r][j] + embedding -> X^T [c][n]*dinv[n] (hi/lo) ----
    for (int i = tid; i < 512; i += 256) {
        int r = i >> 3, chk = i & 7;
        unsigned byte8 = ((chk < 4 ? s_mlo[r] : s_mhi[r]) >> ((chk & 3) * 8)) & 0xFF;
        uint4 v; uint32_t* vp = (uint32_t*)&v;
        #pragma unroll
        for (int j = 0; j < 4; j++) {
            unsigned b2 = (byte8 >> (2 * j)) & 3;
            vp[j] = ((b2 & 1) ? 0x3F80u : 0u) | ((b2 & 2) ? 0x3F800000u : 0u);
        }
        *(uint4*)(sm + ADJ_O + r * ST + chk * 16) = v;
    }
    for (int it = 0; it < 8; it++) {
        int idx = tid + it * 256, c = idx & 63, nn0 = (idx >> 6) * 2;
        float e[2];
        #pragma unroll
        for (int q = 0; q < 2; q++) {
            int n = nn0 + q; float acc;
            if (n < 63) {
                acc = b_dev[c];
                const float* o = s_obs + n * 14;
                #pragma unroll
                for (int k = 0; k < 14; k++) acc = fmaf(o[k], s_ew[k * 64 + c], acc);
            } else {
                acc = b_srv[c];
                #pragma unroll
                for (int k = 0; k < 3; k++) acc = fmaf(s_obs[882 + k], s_ew[896 + k * 64 + c], acc);
            }
            e[q] = fmaxf(acc, 0.0f) * s_dinv[n];
        }
        uint32_t lo, hi = sp2(e[0], e[1], lo);
        *(uint32_t*)(sm + XTH_O + c * ST + nn0 * 2) = hi;
        *(uint32_t*)(sm + XTL_O + c * ST + nn0 * 2) = lo;
    }
    __syncthreads();

    // ---- 3 GCN layers ----
    #pragma unroll 1
    for (int L = 0; L < 3; L++) {
        {   // stage W^T hi/lo + bias
            const uint4* wh = (const uint4*)g_WT[L][0];
            const uint4* wl = (const uint4*)g_WT[L][1];
            for (int i = tid; i < 576; i += 256) {
                ((uint4*)(sm + WH_O))[i] = wh[i];
                ((uint4*)(sm + WL_O))[i] = wl[i];
            }
            const float* bl = (L == 0) ? b1 : (L == 1) ? b2 : b3;
            if (tid < 64) s_bias[tid] = bl[tid];
        }
        // aggregation: D = Adj @ X^T(hi)ᵀ + Adj @ X^T(lo)ᵀ
        float acc[4][4];
        #pragma unroll
        for (int i = 0; i < 4; i++) { acc[i][0]=acc[i][1]=acc[i][2]=acc[i][3]=0.f; }
        gprod(sb + ADJ_O + m0 * ST, sb + XTH_O + n0 * ST, lane, acc);
        gprod(sb + ADJ_O + m0 * ST, sb + XTL_O + n0 * ST, lane, acc);
        __syncthreads();   // W staged; all XT/Adj reads done

        // epi1: T[r][c] = dinv[r]*D  -> TH/TL
        const int r0 = m0 + g, r1 = r0 + 8;
        float d0 = s_dinv[r0], d1 = s_dinv[r1];
        #pragma unroll
        for (int nt = 0; nt < 4; nt++) {
            int c0 = n0 + nt * 8 + c0b;
            uint32_t lo, hi;
            hi = sp2(acc[nt][0] * d0, acc[nt][1] * d0, lo);
            *(uint32_t*)(sm + TH_O + r0 * ST + c0 * 2) = hi;
            *(uint32_t*)(sm + TL_O + r0 * ST + c0 * 2) = lo;
            hi = sp2(acc[nt][2] * d1, acc[nt][3] * d1, lo);
            *(uint32_t*)(sm + TH_O + r1 * ST + c0 * 2) = hi;
            *(uint32_t*)(sm + TL_O + r1 * ST + c0 * 2) = lo;
        }
        __syncthreads();   // T visible

        // layer GEMM: D = T@W = Thi·Whi + Tlo·Whi + Thi·Wlo
        #pragma unroll
        for (int i = 0; i < 4; i++) { acc[i][0]=acc[i][1]=acc[i][2]=acc[i][3]=0.f; }
        gprod(sb + TH_O + m0 * ST, sb + WH_O + n0 * ST, lane, acc);
        gprod(sb + TL_O + m0 * ST, sb + WH_O + n0 * ST, lane, acc);
        gprod(sb + TH_O + m0 * ST, sb + WL_O + n0 * ST, lane, acc);

        if (L < 2) {
            // epi2: X^T_next[c][r] = relu(D+b[c])*dinv[r]  (transposed scatter)
            #pragma unroll
            for (int nt = 0; nt < 4; nt++) {
                int c0 = n0 + nt * 8 + c0b;
                float v00 = fmaxf(acc[nt][0] + s_bias[c0],     0.f) * d0;
                float v01 = fmaxf(acc[nt][1] + s_bias[c0 + 1], 0.f) * d0;
                float v10 = fmaxf(acc[nt][2] + s_bias[c0],     0.f) * d1;
                float v11 = fmaxf(acc[nt][3] + s_bias[c0 + 1], 0.f) * d1;
                uint16_t h, l;
                sp1(v00, h, l);
                *(uint16_t*)(sm + XTH_O + c0 * ST + r0 * 2) = h;
                *(uint16_t*)(sm + XTL_O + c0 * ST + r0 * 2) = l;
                sp1(v01, h, l);
                *(uint16_t*)(sm + XTH_O + (c0 + 1) * ST + r0 * 2) = h;
                *(uint16_t*)(sm + XTL_O + (c0 + 1) * ST + r0 * 2) = l;
                sp1(v10, h, l);
                *(uint16_t*)(sm + XTH_O + c0 * ST + r1 * 2) = h;
                *(uint16_t*)(sm + XTL_O + c0 * ST + r1 * 2) = l;
                sp1(v11, h, l);
                *(uint16_t*)(sm + XTH_O + (c0 + 1) * ST + r1 * 2) = h;
                *(uint16_t*)(sm + XTL_O + (c0 + 1) * ST + r1 * 2) = l;
            }
        } else {
            // epi3: h3[r][c] = relu(D+b[c])  -> hi in ADJ region, lo in XTH region
            #pragma unroll
            for (int nt = 0; nt < 4; nt++) {
                int c0 = n0 + nt * 8 + c0b;
                uint32_t lo, hi;
                hi = sp2(fmaxf(acc[nt][0] + s_bias[c0], 0.f),
                         fmaxf(acc[nt][1] + s_bias[c0 + 1], 0.f), lo);
                *(uint32_t*)(sm + ADJ_O + r0 * ST + c0 * 2) = hi;
                *(uint32_t*)(sm + XTH_O + r0 * ST + c0 * 2) = lo;
                hi = sp2(fmaxf(acc[nt][2] + s_bias[c0], 0.f),
                         fmaxf(acc[nt][3] + s_bias[c0 + 1], 0.f), lo);
                *(uint32_t*)(sm + ADJ_O + r1 * ST + c0 * 2) = hi;
                *(uint32_t*)(sm + XTH_O + r1 * ST + c0 * 2) = lo;
            }
        }
        __syncthreads();
    }

    // ---- head prep: mean + server row || stage Wf1^T (hi: WH rows0-63, TH rows64-127; lo: WL/TL) ----
    if (tid < 64) {
        float s = 0.0f;
        for (int r = 0; r < 63; r++) s += rdbf(sm, ADJ_O, r, tid) + rdbf(sm, XTH_O, r, tid);
        s_mean[tid] = s * (1.0f / 63.0f);
        s_h3s[tid] = rdbf(sm, ADJ_O, 63, tid) + rdbf(sm, XTH_O, 63, tid);
    } else {
        const uint4* hh = (const uint4*)g_Wf1T[0];
        const uint4* hl = (const uint4*)g_Wf1T[1];
        for (int i = tid - 64; i < 1152; i += 192) {
            uint4 vh = hh[i], vl = hl[i];
            if (i < 576) {
                ((uint4*)(sm + WH_O))[i] = vh;
                ((uint4*)(sm + WL_O))[i] = vl;
            } else {
                ((uint4*)(sm + TH_O))[i - 576] = vh;
                ((uint4*)(sm + TL_O))[i - 576] = vl;
            }
        }
    }
    __syncthreads();
    if (tid < 128) {
        float acc = bf1[tid];
        #pragma unroll 4
        for (int k = 0; k < 64; k++) acc = fmaf(s_mean[k], Wf1[(64 + k) * 128 + tid], acc);
        #pragma unroll 4
        for (int k = 0; k < 64; k++) acc = fmaf(s_h3s[k], Wf1[(128 + k) * 128 + tid], acc);
        s_u[tid] = acc;
    } else if (tid - 128 < 128) {
        s_wf2[tid - 128] = Wf2[tid - 128];
    }
    __syncthreads();

    // ---- head GEMM: Z(16x64 per warp) = h3 @ Wf1dev^T, two 32-col half passes ----
    {
        const uint32_t hiB = sb + (ch2 ? TH_O : WH_O);
        const uint32_t loB = sb + (ch2 ? TL_O : WL_O);
        float p0 = 0.f, p1 = 0.f;
        #pragma unroll 1
        for (int h = 0; h < 2; h++) {
            float acc[4][4];
            #pragma unroll
            for (int i = 0; i < 4; i++) { acc[i][0]=acc[i][1]=acc[i][2]=acc[i][3]=0.f; }
            uint32_t boff = (uint32_t)(h * 32 * ST);
            gprod(sb + ADJ_O + m0 * ST, hiB + boff, lane, acc);
            gprod(sb + XTH_O + m0 * ST, hiB + boff, lane, acc);
            gprod(sb + ADJ_O + m0 * ST, loB + boff, lane, acc);
            #pragma unroll
            for (int nt = 0; nt < 4; nt++) {
                int c0 = ch2 * 64 + h * 32 + nt * 8 + c0b;
                float u0 = s_u[c0], u1 = s_u[c0 + 1], w0 = s_wf2[c0], w1 = s_wf2[c0 + 1];
                p0 = fmaf(fmaxf(acc[nt][0] + u0, 0.f), w0, p0);
                p0 = fmaf(fmaxf(acc[nt][1] + u1, 0.f), w1, p0);
                p1 = fmaf(fmaxf(acc[nt][2] + u0, 0.f), w0, p1);
                p1 = fmaf(fmaxf(acc[nt][3] + u1, 0.f), w1, p1);
            }
        }
        p0 += __shfl_xor_sync(0xffffffffu, p0, 1); p0 += __shfl_xor_sync(0xffffffffu, p0, 2);
        p1 += __shfl_xor_sync(0xffffffffu, p1, 1); p1 += __shfl_xor_sync(0xffffffffu, p1, 2);
        if ((lane & 3) == 0) {
            s_part[ch2 * 64 + m0 + g] = p0;
            s_part[ch2 * 64 + m0 + g + 8] = p1;
        }
    }
    __syncthreads();
    if (tid < 63) out[(size_t)b * 63 + tid] = s_part[tid] + s_part[64 + tid] + bf2[0];
}

extern "C" void kernel_launch(void* const* d_in, const int* in_sizes, int n_in,
                              void* d_out, int out_size)
{
    (void)in_sizes; (void)n_in; (void)out_size;
    cudaFuncSetAttribute(pgcn_main, cudaFuncAttributeMaxDynamicSharedMemorySize, SMEM_BYTES);
    pgcn_prep<<<64, 256>>>((const float*)d_in[7], (const float*)d_in[9],
                           (const float*)d_in[11], (const float*)d_in[13]);
    pgcn_main<<<16384, 256, SMEM_BYTES>>>(
        (const float*)d_in[0],  (const float*)d_in[1],  (const float*)d_in[2],
        (const float*)d_in[3],  (const float*)d_in[4],  (const float*)d_in[5],
        (const float*)d_in[6],  (const float*)d_in[8],  (const float*)d_in[10],
        (const float*)d_in[12], (const float*)d_in[13], (const float*)d_in[14],
        (const float*)d_in[15], (const float*)d_in[16], (float*)d_out);
}

// round 8
// speedup vs baseline: 4.2240x; 1.0683x over previous
#include <cuda_runtime.h>
#include <cuda_bf16.h>
#include <cstdint>

#define ST 144                  // row stride bytes (72 bf16): bank-rotating, 16B-aligned
#define ADJ_O 0                 // adjacency -> h3 hi
#define XH_O  9216              // X^T hi / T hi / h3 lo
#define XL_O  18432             // X^T lo / T lo
#define WH_O  27648             // W^T hi (obs scratch pre-loop; head: Wf1^T half hi)
#define WL_O  36864             // W^T lo (ew scratch pre-loop; head: Wf1^T half lo)
#define MLO_O  46080
#define MHI_O  46336
#define DINV_O 46592
#define BIAS_O 46848
#define U_O    47104
#define WF2_O  47616
#define MEAN_O 48128
#define H3S_O  48384
#define PART_O 48640            // float[2][64]
#define SMEM_BYTES 49152

static __device__ __align__(16) unsigned char g_WT[3][2][9216];   // W_L^T [n][k] hi/lo
static __device__ __align__(16) unsigned char g_Wf1T[2][18432];   // Wf1_dev^T [m][k] hi/lo

__device__ __forceinline__ uint32_t smem_u32(const void* p) {
    uint32_t a;
    asm("{ .reg .u64 t; cvta.to.shared.u64 t, %1; cvt.u32.u64 %0, t; }" : "=r"(a) : "l"(p));
    return a;
}
__device__ __forceinline__ void ldsm4(uint32_t addr, uint32_t* r) {
    asm volatile("ldmatrix.sync.aligned.m8n8.x4.shared.b16 {%0,%1,%2,%3}, [%4];"
                 : "=r"(r[0]), "=r"(r[1]), "=r"(r[2]), "=r"(r[3]) : "r"(addr));
}
__device__ __forceinline__ void mma16816(float* d, const uint32_t* a, const uint32_t* b) {
    asm volatile("mma.sync.aligned.m16n8k16.row.col.f32.bf16.bf16.f32 "
        "{%0,%1,%2,%3}, {%4,%5,%6,%7}, {%8,%9}, {%0,%1,%2,%3};"
        : "+f"(d[0]), "+f"(d[1]), "+f"(d[2]), "+f"(d[3])
        : "r"(a[0]), "r"(a[1]), "r"(a[2]), "r"(a[3]), "r"(b[0]), "r"(b[1]));
}
__device__ __forceinline__ void sp1(float v, uint16_t& h, uint16_t& l) {
    __nv_bfloat16 hb = __float2bfloat16(v);
    __nv_bfloat16 lb = __float2bfloat16(v - __bfloat162float(hb));
    h = __bfloat16_as_ushort(hb); l = __bfloat16_as_ushort(lb);
}
__device__ __forceinline__ uint32_t sp2(float a, float b, uint32_t& lo) {
    uint16_t ah, al, bh, bl; sp1(a, ah, al); sp1(b, bh, bl);
    lo = (uint32_t)al | ((uint32_t)bl << 16);
    return (uint32_t)ah | ((uint32_t)bh << 16);
}
__device__ __forceinline__ float rdbf(const unsigned char* sm, int off, int r, int c) {
    return __bfloat162float(*(const __nv_bfloat16*)(sm + off + r * ST + c * 2));
}
// D(16x32) += A_img[m0..][k] @ B_img[n0..][k]^T over K=64; acc = 4 n-tiles x 4
__device__ __forceinline__ void gprod(uint32_t aB, uint32_t bB, int lane, float (*acc)[4]) {
    const int arow = lane & 15, acol = (lane >> 4) << 3;
    const int brow = (lane & 7) + ((lane & 16) >> 1), bcol = lane & 8;
    #pragma unroll
    for (int kk = 0; kk < 64; kk += 16) {
        uint32_t a[4]; ldsm4(aB + arow * ST + (kk + acol) * 2, a);
        #pragma unroll
        for (int nt = 0; nt < 2; nt++) {
            uint32_t bf[4]; ldsm4(bB + (nt * 16 + brow) * ST + (kk + bcol) * 2, bf);
            mma16816(acc[nt * 2], a, bf);
            mma16816(acc[nt * 2 + 1], a, bf + 2);
        }
    }
}

__global__ void pgcn_prep(const float* __restrict__ W1, const float* __restrict__ W2,
                          const float* __restrict__ W3, const float* __restrict__ Wf1) {
    const float* Ws[3] = {W1, W2, W3};
    int gt = blockIdx.x * blockDim.x + threadIdx.x, nth = gridDim.x * blockDim.x;
    for (int L = 0; L < 3; L++)
        for (int i = gt; i < 4096; i += nth) {
            int n = i >> 6, k = i & 63;
            uint16_t h, l; sp1(Ws[L][k * 64 + n], h, l);
            *(uint16_t*)(g_WT[L][0] + n * ST + k * 2) = h;
            *(uint16_t*)(g_WT[L][1] + n * ST + k * 2) = l;
        }
    for (int i = gt; i < 8192; i += nth) {
        int m = i >> 6, k = i & 63;
        uint16_t h, l; sp1(Wf1[k * 128 + m], h, l);
        *(uint16_t*)(g_Wf1T[0] + m * ST + k * 2) = h;
        *(uint16_t*)(g_Wf1T[1] + m * ST + k * 2) = l;
    }
}

__global__ __launch_bounds__(256, 4)
void pgcn_main(const float* __restrict__ dev_obs, const float* __restrict__ srv_obs,
               const float* __restrict__ adj,
               const float* __restrict__ W_dev, const float* __restrict__ b_dev,
               const float* __restrict__ W_srv, const float* __restrict__ b_srv,
               const float* __restrict__ b1, const float* __restrict__ b2,
               const float* __restrict__ b3,
               const float* __restrict__ Wf1, const float* __restrict__ bf1,
               const float* __restrict__ Wf2, const float* __restrict__ bf2,
               float* __restrict__ out)
{
    extern __shared__ __align__(16) unsigned char sm[];
    const uint32_t sb = smem_u32(sm);
    unsigned* s_mlo = (unsigned*)(sm + MLO_O);
    unsigned* s_mhi = (unsigned*)(sm + MHI_O);
    float* s_dinv = (float*)(sm + DINV_O);
    float* s_bias = (float*)(sm + BIAS_O);
    float* s_u    = (float*)(sm + U_O);
    float* s_wf2  = (float*)(sm + WF2_O);
    float* s_mean = (float*)(sm + MEAN_O);
    float* s_h3s  = (float*)(sm + H3S_O);
    float* s_part = (float*)(sm + PART_O);

    const int tid = threadIdx.x, lane = tid & 31, wid = tid >> 5;
    const int b = blockIdx.x;
    const int m0 = (wid & 3) * 16, ch2 = wid >> 2, n0 = ch2 * 32;
    const int g = lane >> 2, c0b = (lane & 3) * 2;

    // ---- stage obs (WH scratch) + emb weights (WL scratch), masks + dinv ----
    float* s_obs = (float*)(sm + WH_O);
    float* s_ew  = (float*)(sm + WL_O);
    for (int i = tid; i < 882; i += 256) s_obs[i] = dev_obs[(size_t)b * 882 + i];
    if (tid < 3) s_obs[882 + tid] = srv_obs[b * 3 + tid];
    for (int i = tid; i < 896; i += 256) s_ew[i] = W_dev[i];
    if (tid < 192) s_ew[896 + tid] = W_srv[tid];
    {
        const float* ar = adj + (size_t)b * 4096;
        for (int r = wid; r < 64; r += 8) {
            unsigned a0 = __ballot_sync(0xffffffffu, ar[r * 64 + lane] != 0.0f);
            unsigned a1 = __ballot_sync(0xffffffffu, ar[r * 64 + 32 + lane] != 0.0f);
            if (lane == 0) {
                s_mlo[r] = a0; s_mhi[r] = a1;
                s_dinv[r] = rsqrtf(fmaxf((float)(__popc(a0) + __popc(a1)), 1.0f));
            }
        }
    }
    __syncthreads();

    // ---- adjacency bf16 tile + embedding -> X^T [c][n]*dinv[n] hi/lo ----
    for (int i = tid; i < 512; i += 256) {
        int r = i >> 3, chk = i & 7;
        unsigned byte8 = ((chk < 4 ? s_mlo[r] : s_mhi[r]) >> ((chk & 3) * 8)) & 0xFF;
        uint4 v; uint32_t* vp = (uint32_t*)&v;
        #pragma unroll
        for (int j = 0; j < 4; j++) {
            unsigned b2 = (byte8 >> (2 * j)) & 3;
            vp[j] = ((b2 & 1) ? 0x3F80u : 0u) | ((b2 & 2) ? 0x3F800000u : 0u);
        }
        *(uint4*)(sm + ADJ_O + r * ST + chk * 16) = v;
    }
    for (int it = 0; it < 8; it++) {
        int idx = tid + it * 256, c = idx & 63, nn0 = (idx >> 6) * 2;
        float e[2];
        #pragma unroll
        for (int q = 0; q < 2; q++) {
            int n = nn0 + q; float acc;
            if (n < 63) {
                acc = b_dev[c];
                const float* o = s_obs + n * 14;
                #pragma unroll
                for (int k = 0; k < 14; k++) acc = fmaf(o[k], s_ew[k * 64 + c], acc);
            } else {
                acc = b_srv[c];
                #pragma unroll
                for (int k = 0; k < 3; k++) acc = fmaf(s_obs[882 + k], s_ew[896 + k * 64 + c], acc);
            }
            e[q] = fmaxf(acc, 0.0f) * s_dinv[n];
        }
        uint32_t lo, hi = sp2(e[0], e[1], lo);
        *(uint32_t*)(sm + XH_O + c * ST + nn0 * 2) = hi;
        *(uint32_t*)(sm + XL_O + c * ST + nn0 * 2) = lo;
    }
    __syncthreads();

    // ---- 3 GCN layers ----
    #pragma unroll 1
    for (int L = 0; L < 3; L++) {
        {   // stage W^T hi/lo + bias (WH/WL free at this point)
            const uint4* wh = (const uint4*)g_WT[L][0];
            const uint4* wl = (const uint4*)g_WT[L][1];
            for (int i = tid; i < 576; i += 256) {
                ((uint4*)(sm + WH_O))[i] = wh[i];
                ((uint4*)(sm + WL_O))[i] = wl[i];
            }
            const float* bl = (L == 0) ? b1 : (L == 1) ? b2 : b3;
            if (tid < 64) s_bias[tid] = bl[tid];
        }
        // aggregation: D[r][c] = Adj @ X^T(hi)ᵀ + Adj @ X^T(lo)ᵀ
        float acc[4][4];
        #pragma unroll
        for (int i = 0; i < 4; i++) { acc[i][0]=acc[i][1]=acc[i][2]=acc[i][3]=0.f; }
        gprod(sb + ADJ_O + m0 * ST, sb + XH_O + n0 * ST, lane, acc);
        gprod(sb + ADJ_O + m0 * ST, sb + XL_O + n0 * ST, lane, acc);
        __syncthreads();   // all X reads done; W staged

        // epi1: T[r][c] = dinv[r]*D -> overwrite XH/XL (T tiles)
        {
            const int r0 = m0 + g, r1 = r0 + 8;
            float d0 = s_dinv[r0], d1 = s_dinv[r1];
            #pragma unroll
            for (int nt = 0; nt < 4; nt++) {
                int c0 = n0 + nt * 8 + c0b;
                uint32_t lo, hi;
                hi = sp2(acc[nt][0] * d0, acc[nt][1] * d0, lo);
                *(uint32_t*)(sm + XH_O + r0 * ST + c0 * 2) = hi;
                *(uint32_t*)(sm + XL_O + r0 * ST + c0 * 2) = lo;
                hi = sp2(acc[nt][2] * d1, acc[nt][3] * d1, lo);
                *(uint32_t*)(sm + XH_O + r1 * ST + c0 * 2) = hi;
                *(uint32_t*)(sm + XL_O + r1 * ST + c0 * 2) = lo;
            }
        }
        __syncthreads();   // T visible

        #pragma unroll
        for (int i = 0; i < 4; i++) { acc[i][0]=acc[i][1]=acc[i][2]=acc[i][3]=0.f; }
        if (L < 2) {
            // gemm (transposed out): D[c][r] = Wᵀ @ Tᵀ = Whi·Thi + Whi·Tlo + Wlo·Thi
            gprod(sb + WH_O + m0 * ST, sb + XH_O + n0 * ST, lane, acc);
            gprod(sb + WH_O + m0 * ST, sb + XL_O + n0 * ST, lane, acc);
            gprod(sb + WL_O + m0 * ST, sb + XH_O + n0 * ST, lane, acc);
            __syncthreads();   // all T reads done
            // epi2: X^T[c][r] = relu(D + b[c]) * dinv[r], packed along r
            const int cA0 = m0 + g, cA1 = cA0 + 8;
            float bA0 = s_bias[cA0], bA1 = s_bias[cA1];
            #pragma unroll
            for (int nt = 0; nt < 4; nt++) {
                int r0 = n0 + nt * 8 + c0b;
                float da = s_dinv[r0], db = s_dinv[r0 + 1];
                uint32_t lo, hi;
                hi = sp2(fmaxf(acc[nt][0] + bA0, 0.f) * da,
                         fmaxf(acc[nt][1] + bA0, 0.f) * db, lo);
                *(uint32_t*)(sm + XH_O + cA0 * ST + r0 * 2) = hi;
                *(uint32_t*)(sm + XL_O + cA0 * ST + r0 * 2) = lo;
                hi = sp2(fmaxf(acc[nt][2] + bA1, 0.f) * da,
                         fmaxf(acc[nt][3] + bA1, 0.f) * db, lo);
                *(uint32_t*)(sm + XH_O + cA1 * ST + r0 * 2) = hi;
                *(uint32_t*)(sm + XL_O + cA1 * ST + r0 * 2) = lo;
            }
        } else {
            // gemm3: D[r][c] = T @ Wᵀ (node-major h3)
            gprod(sb + XH_O + m0 * ST, sb + WH_O + n0 * ST, lane, acc);
            gprod(sb + XL_O + m0 * ST, sb + WH_O + n0 * ST, lane, acc);
            gprod(sb + XH_O + m0 * ST, sb + WL_O + n0 * ST, lane, acc);
            __syncthreads();
            // epi3: h3 = relu(D + b[c]); hi->ADJ, lo->XH
            const int r0 = m0 + g, r1 = r0 + 8;
            #pragma unroll
            for (int nt = 0; nt < 4; nt++) {
                int c0 = n0 + nt * 8 + c0b;
                float b0v = s_bias[c0], b1v = s_bias[c0 + 1];
                uint32_t lo, hi;
                hi = sp2(fmaxf(acc[nt][0] + b0v, 0.f), fmaxf(acc[nt][1] + b1v, 0.f), lo);
                *(uint32_t*)(sm + ADJ_O + r0 * ST + c0 * 2) = hi;
                *(uint32_t*)(sm + XH_O + r0 * ST + c0 * 2) = lo;
                hi = sp2(fmaxf(acc[nt][2] + b0v, 0.f), fmaxf(acc[nt][3] + b1v, 0.f), lo);
                *(uint32_t*)(sm + ADJ_O + r1 * ST + c0 * 2) = hi;
                *(uint32_t*)(sm + XH_O + r1 * ST + c0 * 2) = lo;
            }
        }
        __syncthreads();
    }

    // ---- head prep: mean + server row || stage Wf1^T half 0 ----
    if (tid < 64) {
        float s = 0.0f;
        for (int r = 0; r < 63; r++) s += rdbf(sm, ADJ_O, r, tid) + rdbf(sm, XH_O, r, tid);
        s_mean[tid] = s * (1.0f / 63.0f);
        s_h3s[tid] = rdbf(sm, ADJ_O, 63, tid) + rdbf(sm, XH_O, 63, tid);
    } else {
        const uint4* hh = (const uint4*)g_Wf1T[0];
        const uint4* hl = (const uint4*)g_Wf1T[1];
        for (int i = tid - 64; i < 576; i += 192) {
            ((uint4*)(sm + WH_O))[i] = hh[i];
            ((uint4*)(sm + WL_O))[i] = hl[i];
        }
    }
    __syncthreads();
    // u[m] = bf1 + Wf1_meanᵀ mean + Wf1_srvᵀ h3_srv (fp32, constant over nodes)
    if (tid < 128) {
        float acc = bf1[tid];
        #pragma unroll 4
        for (int k = 0; k < 64; k++) acc = fmaf(s_mean[k], Wf1[(64 + k) * 128 + tid], acc);
        #pragma unroll 4
        for (int k = 0; k < 64; k++) acc = fmaf(s_h3s[k], Wf1[(128 + k) * 128 + tid], acc);
        s_u[tid] = acc;
    } else if (tid - 128 < 128) {
        s_wf2[tid - 128] = Wf2[tid - 128];
    }
    __syncthreads();

    // ---- head GEMM: two half passes over Wf1ᵀ (64 m-cols each) ----
    float p0 = 0.f, p1 = 0.f;
    #pragma unroll 1
    for (int h = 0; h < 2; h++) {
        if (h == 1) {   // restage half 1
            const uint4* hh = (const uint4*)(g_Wf1T[0] + 64 * ST);
            const uint4* hl = (const uint4*)(g_Wf1T[1] + 64 * ST);
            for (int i = tid; i < 576; i += 256) {
                ((uint4*)(sm + WH_O))[i] = hh[i];
                ((uint4*)(sm + WL_O))[i] = hl[i];
            }
            __syncthreads();
        }
        float acc[4][4];
        #pragma unroll
        for (int i = 0; i < 4; i++) { acc[i][0]=acc[i][1]=acc[i][2]=acc[i][3]=0.f; }
        gprod(sb + ADJ_O + m0 * ST, sb + WH_O + n0 * ST, lane, acc);
        gprod(sb + XH_O + m0 * ST, sb + WH_O + n0 * ST, lane, acc);
        gprod(sb + ADJ_O + m0 * ST, sb + WL_O + n0 * ST, lane, acc);
        #pragma unroll
        for (int nt = 0; nt < 4; nt++) {
            int c0 = h * 64 + n0 + nt * 8 + c0b;
            float u0 = s_u[c0], u1 = s_u[c0 + 1], w0 = s_wf2[c0], w1 = s_wf2[c0 + 1];
            p0 = fmaf(fmaxf(acc[nt][0] + u0, 0.f), w0, p0);
            p0 = fmaf(fmaxf(acc[nt][1] + u1, 0.f), w1, p0);
            p1 = fmaf(fmaxf(acc[nt][2] + u0, 0.f), w0, p1);
            p1 = fmaf(fmaxf(acc[nt][3] + u1, 0.f), w1, p1);
        }
        __syncthreads();   // half reads done (safe to restage / finish)
    }
    p0 += __shfl_xor_sync(0xffffffffu, p0, 1); p0 += __shfl_xor_sync(0xffffffffu, p0, 2);
    p1 += __shfl_xor_sync(0xffffffffu, p1, 1); p1 += __shfl_xor_sync(0xffffffffu, p1, 2);
    if ((lane & 3) == 0) {
        s_part[ch2 * 64 + m0 + g] = p0;
        s_part[ch2 * 64 + m0 + g + 8] = p1;
    }
    __syncthreads();
    if (tid < 63) out[(size_t)b * 63 + tid] = s_part[tid] + s_part[64 + tid] + bf2[0];
}

extern "C" void kernel_launch(void* const* d_in, const int* in_sizes, int n_in,
                              void* d_out, int out_size)
{
    (void)in_sizes; (void)n_in; (void)out_size;
    cudaFuncSetAttribute(pgcn_main, cudaFuncAttributeMaxDynamicSharedMemorySize, SMEM_BYTES);
    pgcn_prep<<<64, 256>>>((const float*)d_in[7], (const float*)d_in[9],
                           (const float*)d_in[11], (const float*)d_in[13]);
    pgcn_main<<<16384, 256, SMEM_BYTES>>>(
        (const float*)d_in[0],  (const float*)d_in[1],  (const float*)d_in[2],
        (const float*)d_in[3],  (const float*)d_in[4],  (const float*)d_in[5],
        (const float*)d_in[6],  (const float*)d_in[8],  (const float*)d_in[10],
        (const float*)d_in[12], (const float*)d_in[13], (const float*)d_in[14],
        (const float*)d_in[15], (const float*)d_in[16], (float*)d_out);
}